// round 10
// baseline (speedup 1.0000x reference)
#include <cuda_runtime.h>
#include <cuda_bf16.h>

// ---------------- problem constants ----------------
#define BB 4
#define AA 10
#define LL 4096
#define NPROP (LL * AA)          // 40960 per batch (fits in 16 bits)
#define TOTAL (BB * NPROP)       // 163840
#define PRE_NMS 6000
#define POST_NMS 300
#define NCHUNK ((PRE_NMS + 31) / 32)   // 188
#define NMS_THRESH_F 0.7f
#define MIN_SIZE_F 8.0f
#define FEAT_STRIDE 8
#define CLIP_MAX 32767.0f        // L*FEAT_STRIDE - 1
#define FULLMASK 0xFFFFFFFFu
#define NMS_WARPS 8
#define NMS_THREADS (NMS_WARPS * 32)

#define NBINS 65536
#define SCAN_THREADS 1024
#define BINS_PER_THREAD (NBINS / SCAN_THREADS)   // 64
#define CAP 12288                 // per-batch stored slots (top region + straddle margin)

// ---------------- static device scratch (no allocations allowed) ----------------
__device__ float    g_x1[TOTAL];
__device__ float    g_x2[TOTAL];
__device__ unsigned g_skey[TOTAL];             // orderable score key per element
__device__ unsigned g_hist[BB * NBINS];        // per-batch bin counts
__device__ unsigned g_binstart[BB * NBINS];    // per-batch bin suffix-starts (consumed by scatter)
__device__ unsigned g_sorted[BB * CAP];        // res = (~skey_low16)<<16 | r, rank-ordered

__constant__ float c_scales[AA] = {2.f, 4.f, 5.f, 6.f, 8.f, 9.f, 10.f, 12.f, 14.f, 16.f};

// ---------------- kernel 0: zero histograms ----------------
__global__ void zero_hist() {
    int t = blockIdx.x * blockDim.x + threadIdx.x;   // 65536 threads, uint4 each
    ((uint4*)g_hist)[t] = make_uint4(0, 0, 0, 0);
}

// ---------------- kernel 1: decode proposals + score keys + histogram ----------------
__global__ void compute_props(const float* __restrict__ scores_in,
                              const float* __restrict__ deltas_in) {
    int t = blockIdx.x * blockDim.x + threadIdx.x;
    if (t >= TOTAL) return;
    int l = t & (LL - 1);
    int ba = t >> 12;                  // b*AA + a
    int b = ba / AA;
    int a = ba - b * AA;

    const int base = b * (2 * AA) * LL;
    float score = scores_in[base + (AA + a) * LL + l];
    float d0    = deltas_in[base + (2 * a) * LL + l];
    float d1    = deltas_in[base + (2 * a + 1) * LL + l];

    float ws   = c_scales[a] * (float)FEAT_STRIDE;
    float ctrA = ((float)FEAT_STRIDE - 1.0f) * 0.5f;      // 3.5
    float shift = (float)(l * FEAT_STRIDE);
    float x1a = ctrA - 0.5f * (ws - 1.0f) + shift;
    float x2a = ctrA + 0.5f * (ws - 1.0f) + shift;

    float width = x2a - x1a + 1.0f;
    float ctr   = x1a + 0.5f * width;

    float pred_ctr = d0 * width + ctr;
    float pred_l   = expf(d1) * width;

    float x1 = pred_ctr - 0.5f * pred_l;
    float x2 = pred_ctr + 0.5f * pred_l;
    x1 = fminf(fmaxf(x1, 0.0f), CLIP_MAX);
    x2 = fminf(fmaxf(x2, 0.0f), CLIP_MAX);

    float ls = x2 - x1 + 1.0f;
    if (ls < MIN_SIZE_F) score = 0.0f;

    int r = l * AA + a;                // reference proposal index within batch
    int idx = b * NPROP + r;
    g_x1[idx] = x1;
    g_x2[idx] = x2;

    // monotone float -> uint mapping (ascending float -> ascending key)
    unsigned u = __float_as_uint(score);
    unsigned skey = (u & 0x80000000u) ? ~u : (u | 0x80000000u);
    g_skey[idx] = skey;
    atomicAdd(&g_hist[b * NBINS + (skey >> 16)], 1u);
}

// ---------------- kernel 2: per-batch suffix scan of bins -> descending-rank starts ----
// Streaming (no per-thread arrays): read hist twice; 2nd read is L1-resident.
__global__ void __launch_bounds__(SCAN_THREADS) scan_kernel() {
    __shared__ unsigned s_part[SCAN_THREADS];
    __shared__ unsigned s_total;
    const int b = blockIdx.x;
    const int tid = threadIdx.x;
    const unsigned* hist  = g_hist     + b * NBINS;
    unsigned*       start = g_binstart + b * NBINS;
    const int base = tid * BINS_PER_THREAD;

    // pass 1: per-thread sum
    unsigned sum = 0;
    #pragma unroll 8
    for (int k = 0; k < BINS_PER_THREAD; ++k) sum += hist[base + k];
    s_part[tid] = sum;
    __syncthreads();
    // inclusive Hillis-Steele scan over thread sums
    for (int off = 1; off < SCAN_THREADS; off <<= 1) {
        unsigned v = (tid >= off) ? s_part[tid - off] : 0u;
        __syncthreads();
        s_part[tid] += v;
        __syncthreads();
    }
    if (tid == SCAN_THREADS - 1) s_total = s_part[tid];
    __syncthreads();
    // elements strictly above this thread's bin range (inclusive scan includes own sum)
    unsigned above = s_total - s_part[tid] + sum;

    // pass 2: running suffix within the thread's range, high bin -> low bin
    unsigned suf = above - sum;        // = elements in bins above the whole range
    for (int k = BINS_PER_THREAD - 1; k >= 0; --k) {
        start[base + k] = suf;
        suf += hist[base + k];
    }
}

// ---------------- kernel 3: scatter elements to rank slots ----------------
__global__ void scatter_kernel() {
    int idx = blockIdx.x * blockDim.x + threadIdx.x;
    if (idx >= TOTAL) return;
    int b = idx / NPROP;
    int r = idx - b * NPROP;
    unsigned skey = g_skey[idx];
    unsigned bin  = skey >> 16;
    unsigned slot = atomicAdd(&g_binstart[b * NBINS + bin], 1u);
    if (slot < CAP) {
        unsigned res = (((~skey) & 0xFFFFu) << 16) | (unsigned)r;
        g_sorted[b * CAP + slot] = res;
    }
}

// ---------------- kernel 4: per-bin insertion sort (restores exact order) ----------------
__global__ void binsort_kernel() {
    int t = blockIdx.x * blockDim.x + threadIdx.x;
    if (t >= BB * NBINS) return;
    unsigned cnt = g_hist[t];
    if (cnt < 2) return;
    unsigned end_  = g_binstart[t];      // == start + cnt after scatter
    unsigned start = end_ - cnt;
    if (start >= PRE_NMS) return;        // bin entirely outside top region
    if (end_ > CAP) end_ = CAP;
    int b = t >> 16;
    unsigned* arr = g_sorted + b * CAP;
    for (unsigned i = start + 1; i < end_; ++i) {
        unsigned v = arr[i];
        unsigned j = i;
        while (j > start && arr[j - 1] > v) { arr[j] = arr[j - 1]; --j; }
        arr[j] = v;
    }
}

// ---------------- kernel 5: fused gather + multi-warp greedy NMS (1 block / batch) ----
// dynamic smem: scand[PRE_NMS] float2 (48000 B) + skept[POST_NMS] float4 (4800 B)
__global__ void nms_fused(float* __restrict__ out) {
    extern __shared__ unsigned char smem_raw[];
    float2* scand = (float2*)smem_raw;
    float4* skept = (float4*)(scand + PRE_NMS);
    __shared__ unsigned s_sup[NMS_WARPS];
    __shared__ unsigned s_rowp[NMS_WARPS][32];
    __shared__ int s_K;

    const int b    = blockIdx.x;
    const int tid  = threadIdx.x;
    const int wid  = tid >> 5;
    const int lane = tid & 31;

    // gather top-PRE_NMS boxes (rank order) into shared; init output
    const unsigned* __restrict__ srt = g_sorted + b * CAP;
    for (int i = tid; i < PRE_NMS; i += NMS_THREADS) {
        int r = (int)(srt[i] & 0xFFFFu);
        int gi = b * NPROP + r;
        scand[i] = make_float2(g_x1[gi], g_x2[gi]);
    }
    for (int i = tid; i < POST_NMS; i += NMS_THREADS) {
        float* o = out + (b * POST_NMS + i) * 3;
        o[0] = (float)b; o[1] = 0.0f; o[2] = 0.0f;
    }
    if (tid == 0) s_K = 0;
    __syncthreads();

    for (int c = 0; c < NCHUNK; ++c) {
        const int i = c * 32 + lane;
        const bool valid = (i < PRE_NMS);
        const int nvalid = PRE_NMS - c * 32;
        const unsigned validMask =
            (nvalid >= 32) ? FULLMASK : ((1u << nvalid) - 1u);

        float x1 = 0.0f, x2 = -2.0f;
        if (valid) { float2 t0 = scand[i]; x1 = t0.x; x2 = t0.y; }
        const float len = x2 - x1 + 1.0f;
        const int K = s_K;

        // ---- phase 1 (all 8 warps): candidate vs kept list, j strided by warp ----
        bool sup = !valid;
        int it = 0;
        for (int j = wid; j < K; j += NMS_WARPS) {
            float4 kb = skept[j];                    // broadcast within warp
            float inter = fminf(x2, kb.y) - fmaxf(x1, kb.x) + 1.0f;
            float uni = len + kb.z - inter;
            if (inter > 0.6999f * uni) {             // prefilter; decision by division
                if (inter / uni > NMS_THRESH_F) sup = true;
            }
            if (((++it) & 3) == 0 && __all_sync(FULLMASK, sup)) break;
        }
        {
            unsigned bal = __ballot_sync(FULLMASK, sup);
            if (lane == 0) s_sup[wid] = bal;
        }

        // ---- phase 2 (all 8 warps): split intra-chunk butterfly, <=4 offsets each ----
        {
            unsigned rowp = 0u;
            const int d0 = 4 * wid + 1;
            const int d1 = (4 * wid + 4 < 32) ? 4 * wid + 4 : 31;
            for (int d = d0; d <= d1; ++d) {
                float ox1 = __shfl_xor_sync(FULLMASK, x1, d);
                float ox2 = __shfl_xor_sync(FULLMASK, x2, d);
                float olen = ox2 - ox1 + 1.0f;
                float inter = fminf(x2, ox2) - fmaxf(x1, ox1) + 1.0f;
                float uni = len + olen - inter;
                if (inter > 0.6999f * uni) {
                    if (inter / uni > NMS_THRESH_F) rowp |= 1u << (lane ^ d);
                }
            }
            s_rowp[wid][lane] = rowp;
        }
        __syncthreads();

        // ---- phases 3-4 (warp 0 only): resolve + append ----
        if (wid == 0) {
            unsigned removed = ~validMask;
            #pragma unroll
            for (int w = 0; w < NMS_WARPS; ++w) removed |= s_sup[w];

            unsigned row = 0u;
            #pragma unroll
            for (int w = 0; w < NMS_WARPS; ++w) row |= s_rowp[w][lane];
            row &= validMask;

            // serial greedy resolution of the chunk
            unsigned keptbits = 0u;
            unsigned alive = ~removed;
            while (alive) {
                int p = __ffs(alive) - 1;                       // uniform
                keptbits |= 1u << p;
                unsigned rowp = __shfl_sync(FULLMASK, row, p);
                removed |= rowp;
                alive = ~removed & ~((2u << p) - 1u);
            }

            // append kept boxes
            int nk = __popc(keptbits);
            if (nk) {
                int myrank = K + __popc(keptbits & ((1u << lane) - 1u));
                if (((keptbits >> lane) & 1u) && myrank < POST_NMS) {
                    skept[myrank] = make_float4(x1, x2, len, 0.0f);
                    float* o = out + (b * POST_NMS + myrank) * 3;
                    o[1] = x1; o[2] = x2;
                }
                if (lane == 0) s_K = K + nk;
            }
        }
        __syncthreads();
        if (s_K >= POST_NMS) break;
    }
}

// ---------------- host launcher ----------------
extern "C" void kernel_launch(void* const* d_in, const int* in_sizes, int n_in,
                              void* d_out, int out_size) {
    (void)in_sizes; (void)n_in; (void)out_size;
    const float* scores = (const float*)d_in[0];
    const float* deltas = (const float*)d_in[1];
    float* out = (float*)d_out;

    zero_hist<<<(BB * NBINS / 4) / 256, 256>>>();
    compute_props<<<(TOTAL + 255) / 256, 256>>>(scores, deltas);
    scan_kernel<<<BB, SCAN_THREADS>>>();
    scatter_kernel<<<(TOTAL + 255) / 256, 256>>>();
    binsort_kernel<<<(BB * NBINS + 255) / 256, 256>>>();

    const int smem_bytes = PRE_NMS * (int)sizeof(float2) + POST_NMS * (int)sizeof(float4);
    cudaFuncSetAttribute(nms_fused, cudaFuncAttributeMaxDynamicSharedMemorySize, smem_bytes);
    nms_fused<<<BB, NMS_THREADS, smem_bytes>>>(out);
}

// round 11
// speedup vs baseline: 2.9215x; 2.9215x over previous
#include <cuda_runtime.h>
#include <cuda_bf16.h>
#include <cub/cub.cuh>

// ---------------- problem constants ----------------
#define BB 4
#define AA 10
#define LL 4096
#define NPROP (LL * AA)          // 40960 per batch
#define TOTAL (BB * NPROP)       // 163840
#define PRE_NMS 6000
#define POST_NMS 300
#define NCHUNK ((PRE_NMS + 31) / 32)   // 188
#define NMS_THRESH_F 0.7f
#define MIN_SIZE_F 8.0f
#define FEAT_STRIDE 8
#define CLIP_MAX 32767.0f        // L*FEAT_STRIDE - 1
#define FULLMASK 0xFFFFFFFFu
#define NMS_WARPS 8
#define NMS_THREADS (NMS_WARPS * 32)
#define TILE (NMS_THREADS * 4)   // 1024 entries per gather iteration; TOTAL % TILE == 0

// ---------------- static device scratch (no allocations allowed) ----------------
__device__ float2   g_box[TOTAL];          // decoded boxes, reference index order
__device__ unsigned g_key_in[TOTAL];       // ~orderable(score): ascending = score desc
__device__ unsigned g_key_out[TOTAL];
__device__ unsigned g_val_in[TOTAL];       // (b << 20) | r
__device__ unsigned g_val_out[TOTAL];
__device__ unsigned char g_cub_temp[8 << 20];

__constant__ float c_scales[AA] = {2.f, 4.f, 5.f, 6.f, 8.f, 9.f, 10.f, 12.f, 14.f, 16.f};

// ---------------- kernel 1: decode proposals + build sort keys/values ----------------
__global__ void compute_props(const float* __restrict__ scores_in,
                              const float* __restrict__ deltas_in) {
    int t = blockIdx.x * blockDim.x + threadIdx.x;
    if (t >= TOTAL) return;
    int l = t & (LL - 1);
    int ba = t >> 12;                  // b*AA + a
    int b = ba / AA;
    int a = ba - b * AA;

    const int base = b * (2 * AA) * LL;
    float score = scores_in[base + (AA + a) * LL + l];
    float d0    = deltas_in[base + (2 * a) * LL + l];
    float d1    = deltas_in[base + (2 * a + 1) * LL + l];

    float ws   = c_scales[a] * (float)FEAT_STRIDE;
    float ctrA = ((float)FEAT_STRIDE - 1.0f) * 0.5f;      // 3.5
    float shift = (float)(l * FEAT_STRIDE);
    float x1a = ctrA - 0.5f * (ws - 1.0f) + shift;
    float x2a = ctrA + 0.5f * (ws - 1.0f) + shift;

    float width = x2a - x1a + 1.0f;
    float ctr   = x1a + 0.5f * width;

    float pred_ctr = d0 * width + ctr;
    float pred_l   = expf(d1) * width;

    float x1 = pred_ctr - 0.5f * pred_l;
    float x2 = pred_ctr + 0.5f * pred_l;
    x1 = fminf(fmaxf(x1, 0.0f), CLIP_MAX);
    x2 = fminf(fmaxf(x2, 0.0f), CLIP_MAX);

    float ls = x2 - x1 + 1.0f;
    if (ls < MIN_SIZE_F) score = 0.0f;

    int r = l * AA + a;                // reference proposal index within batch
    int idx = b * NPROP + r;
    g_box[idx] = make_float2(x1, x2);

    // monotone float -> uint (ascending); invert so ascending sort = score descending.
    // Stable sort ties (equal score, any batch) keep input order = idx = (b, r) asc,
    // so per-batch order is exactly (score desc, r asc) = reference stable argsort.
    unsigned u = __float_as_uint(score);
    unsigned asc = (u & 0x80000000u) ? ~u : (u | 0x80000000u);
    g_key_in[idx] = ~asc;
    g_val_in[idx] = ((unsigned)b << 20) | (unsigned)r;
}

// ---------------- kernel 2: gather(compact by batch) + multi-warp greedy NMS ----------
// dynamic smem: scand[PRE_NMS] float2 (48000 B) + skept[POST_NMS] float4 (4800 B)
__global__ void nms_fused(float* __restrict__ out) {
    extern __shared__ unsigned char smem_raw[];
    float2* scand = (float2*)smem_raw;
    float4* skept = (float4*)(scand + PRE_NMS);
    __shared__ unsigned s_wcnt[NMS_WARPS];
    __shared__ unsigned s_sup[NMS_WARPS];
    __shared__ unsigned s_rowp[NMS_WARPS][32];
    __shared__ int s_cnt;      // gathered so far
    __shared__ int s_K;        // NMS kept so far

    const int b    = blockIdx.x;
    const int tid  = threadIdx.x;
    const int wid  = tid >> 5;
    const int lane = tid & 31;

    for (int i = tid; i < POST_NMS; i += NMS_THREADS) {
        float* o = out + (b * POST_NMS + i) * 3;
        o[0] = (float)b; o[1] = 0.0f; o[2] = 0.0f;
    }
    if (tid == 0) { s_cnt = 0; s_K = 0; }
    __syncthreads();

    // ---- ordered block compaction: first PRE_NMS sorted entries of batch b ----
    {
        const uint4* __restrict__ vals4 = (const uint4*)g_val_out;
        const float2* __restrict__ box  = g_box;
        for (int base = 0; base < TOTAL && s_cnt < PRE_NMS; base += TILE) {
            uint4 v4 = vals4[(base >> 2) + tid];   // 4 consecutive sorted entries
            unsigned vv[4] = {v4.x, v4.y, v4.z, v4.w};
            bool p[4];
            unsigned c = 0;
            #pragma unroll
            for (int k = 0; k < 4; ++k) {
                p[k] = ((int)(vv[k] >> 20) == b);
                c += p[k];
            }
            // inclusive warp scan of per-thread counts
            unsigned inc = c;
            #pragma unroll
            for (int off = 1; off < 32; off <<= 1) {
                unsigned n = __shfl_up_sync(FULLMASK, inc, off);
                if (lane >= off) inc += n;
            }
            if (lane == 31) s_wcnt[wid] = inc;
            const unsigned excl = inc - c;
            __syncthreads();
            unsigned wbase = 0, total = 0;
            #pragma unroll
            for (int w = 0; w < NMS_WARPS; ++w) {
                unsigned wc = s_wcnt[w];
                if (w < wid) wbase += wc;
                total += wc;
            }
            int o = s_cnt + (int)(wbase + excl);
            #pragma unroll
            for (int k = 0; k < 4; ++k) {
                if (p[k]) {
                    if (o < PRE_NMS) {
                        int r = (int)(vv[k] & 0xFFFFFu);
                        scand[o] = box[b * NPROP + r];
                    }
                    ++o;
                }
            }
            __syncthreads();
            if (tid == 0) s_cnt += (int)total;
            __syncthreads();
        }
    }

    // ---- chunked greedy NMS (same structure as R7) ----
    for (int c = 0; c < NCHUNK; ++c) {
        const int i = c * 32 + lane;
        const bool valid = (i < PRE_NMS);
        const int nvalid = PRE_NMS - c * 32;
        const unsigned validMask =
            (nvalid >= 32) ? FULLMASK : ((1u << nvalid) - 1u);

        float x1 = 0.0f, x2 = -2.0f;
        if (valid) { float2 t0 = scand[i]; x1 = t0.x; x2 = t0.y; }
        const float len = x2 - x1 + 1.0f;
        const int K = s_K;

        // phase 1 (all 8 warps): candidate vs kept list, j strided by warp
        bool sup = !valid;
        int it = 0;
        for (int j = wid; j < K; j += NMS_WARPS) {
            float4 kb = skept[j];                    // broadcast within warp
            float inter = fminf(x2, kb.y) - fmaxf(x1, kb.x) + 1.0f;
            float uni = len + kb.z - inter;
            if (inter > 0.6999f * uni) {             // prefilter; decision by division
                if (inter / uni > NMS_THRESH_F) sup = true;
            }
            if (((++it) & 3) == 0 && __all_sync(FULLMASK, sup)) break;
        }
        {
            unsigned bal = __ballot_sync(FULLMASK, sup);
            if (lane == 0) s_sup[wid] = bal;
        }

        // phase 2 (all 8 warps): split intra-chunk butterfly, <=4 offsets each
        {
            unsigned rowp = 0u;
            const int d0 = 4 * wid + 1;
            const int d1 = (4 * wid + 4 < 32) ? 4 * wid + 4 : 31;
            for (int d = d0; d <= d1; ++d) {
                float ox1 = __shfl_xor_sync(FULLMASK, x1, d);
                float ox2 = __shfl_xor_sync(FULLMASK, x2, d);
                float olen = ox2 - ox1 + 1.0f;
                float inter = fminf(x2, ox2) - fmaxf(x1, ox1) + 1.0f;
                float uni = len + olen - inter;
                if (inter > 0.6999f * uni) {
                    if (inter / uni > NMS_THRESH_F) rowp |= 1u << (lane ^ d);
                }
            }
            s_rowp[wid][lane] = rowp;
        }
        __syncthreads();

        // phases 3-4 (warp 0 only): resolve + append
        if (wid == 0) {
            unsigned removed = ~validMask;
            #pragma unroll
            for (int w = 0; w < NMS_WARPS; ++w) removed |= s_sup[w];

            unsigned row = 0u;
            #pragma unroll
            for (int w = 0; w < NMS_WARPS; ++w) row |= s_rowp[w][lane];
            row &= validMask;

            unsigned keptbits = 0u;
            unsigned alive = ~removed;
            while (alive) {
                int p = __ffs(alive) - 1;                       // uniform
                keptbits |= 1u << p;
                unsigned rowp = __shfl_sync(FULLMASK, row, p);
                removed |= rowp;
                alive = ~removed & ~((2u << p) - 1u);
            }

            int nk = __popc(keptbits);
            if (nk) {
                int myrank = K + __popc(keptbits & ((1u << lane) - 1u));
                if (((keptbits >> lane) & 1u) && myrank < POST_NMS) {
                    skept[myrank] = make_float4(x1, x2, len, 0.0f);
                    float* o = out + (b * POST_NMS + myrank) * 3;
                    o[1] = x1; o[2] = x2;
                }
                if (lane == 0) s_K = K + nk;
            }
        }
        __syncthreads();
        if (s_K >= POST_NMS) break;
    }
}

// ---------------- host launcher ----------------
extern "C" void kernel_launch(void* const* d_in, const int* in_sizes, int n_in,
                              void* d_out, int out_size) {
    (void)in_sizes; (void)n_in; (void)out_size;
    const float* scores = (const float*)d_in[0];
    const float* deltas = (const float*)d_in[1];
    float* out = (float*)d_out;

    unsigned *kin, *kout, *vin, *vout; void* tmp;
    cudaGetSymbolAddress((void**)&kin,  g_key_in);
    cudaGetSymbolAddress((void**)&kout, g_key_out);
    cudaGetSymbolAddress((void**)&vin,  g_val_in);
    cudaGetSymbolAddress((void**)&vout, g_val_out);
    cudaGetSymbolAddress((void**)&tmp,  g_cub_temp);

    compute_props<<<(TOTAL + 255) / 256, 256>>>(scores, deltas);

    // global 32-bit pair sort: 4 onesweep passes (batch recovered in nms gather)
    size_t temp_bytes = sizeof(g_cub_temp);
    cub::DeviceRadixSort::SortPairs(
        tmp, temp_bytes,
        kin, kout, vin, vout, TOTAL,
        0, 32, (cudaStream_t)0);

    const int smem_bytes = PRE_NMS * (int)sizeof(float2) + POST_NMS * (int)sizeof(float4);
    cudaFuncSetAttribute(nms_fused, cudaFuncAttributeMaxDynamicSharedMemorySize, smem_bytes);
    nms_fused<<<BB, NMS_THREADS, smem_bytes>>>(out);
}

// round 12
// speedup vs baseline: 4.3269x; 1.4811x over previous
#include <cuda_runtime.h>
#include <cuda_bf16.h>
#include <cub/cub.cuh>

// ---------------- problem constants ----------------
#define BB 4
#define AA 10
#define LL 4096
#define NPROP (LL * AA)          // 40960 per batch (fits in 16 bits)
#define TOTAL (BB * NPROP)       // 163840
#define PRE_NMS 6000
#define POST_NMS 300
#define NCHUNK ((PRE_NMS + 31) / 32)   // 188
#define NMS_THRESH_F 0.7f
#define MIN_SIZE_F 8.0f
#define FEAT_STRIDE 8
#define CLIP_MAX 32767.0f        // L*FEAT_STRIDE - 1
#define FULLMASK 0xFFFFFFFFu
#define NMS_WARPS 16
#define NMS_THREADS (NMS_WARPS * 32)   // 512

// ---------------- static device scratch (no allocations allowed) ----------------
__device__ float2 g_box[TOTAL];
__device__ unsigned long long g_ckey_in[TOTAL];
__device__ unsigned long long g_ckey_out[TOTAL];
__device__ unsigned char g_cub_temp[8 << 20];

__constant__ float c_scales[AA] = {2.f, 4.f, 5.f, 6.f, 8.f, 9.f, 10.f, 12.f, 14.f, 16.f};

// ---------------- kernel 1: decode proposals + build composite sort keys ----------------
// ckey = (b << 48) | ((~orderable(score)) << 16) | r
// Radix-sorting bits [16,50) ascending => batch-major, score-descending.
// Ties (same batch+score) keep INPUT order (onesweep is stable), and input is
// written at idx = b*NPROP + r => r-ascending, matching the reference argsort.
__global__ void compute_props(const float* __restrict__ scores_in,
                              const float* __restrict__ deltas_in) {
    int t = blockIdx.x * blockDim.x + threadIdx.x;
    if (t >= TOTAL) return;
    int l = t & (LL - 1);
    int ba = t >> 12;                  // b*AA + a
    int b = ba / AA;
    int a = ba - b * AA;

    const int base = b * (2 * AA) * LL;
    float score = scores_in[base + (AA + a) * LL + l];
    float d0    = deltas_in[base + (2 * a) * LL + l];
    float d1    = deltas_in[base + (2 * a + 1) * LL + l];

    float ws   = c_scales[a] * (float)FEAT_STRIDE;
    float ctrA = ((float)FEAT_STRIDE - 1.0f) * 0.5f;      // 3.5
    float shift = (float)(l * FEAT_STRIDE);
    float x1a = ctrA - 0.5f * (ws - 1.0f) + shift;
    float x2a = ctrA + 0.5f * (ws - 1.0f) + shift;

    float width = x2a - x1a + 1.0f;
    float ctr   = x1a + 0.5f * width;

    float pred_ctr = d0 * width + ctr;
    float pred_l   = expf(d1) * width;

    float x1 = pred_ctr - 0.5f * pred_l;
    float x2 = pred_ctr + 0.5f * pred_l;
    x1 = fminf(fmaxf(x1, 0.0f), CLIP_MAX);
    x2 = fminf(fmaxf(x2, 0.0f), CLIP_MAX);

    float ls = x2 - x1 + 1.0f;
    if (ls < MIN_SIZE_F) score = 0.0f;

    int r = l * AA + a;                // reference proposal index within batch
    int idx = b * NPROP + r;
    g_box[idx] = make_float2(x1, x2);

    // monotone float -> uint mapping (ascending float -> ascending key)
    unsigned u = __float_as_uint(score);
    unsigned skey = (u & 0x80000000u) ? ~u : (u | 0x80000000u);
    unsigned long long ckey = ((unsigned long long)b << 48)
                            | ((unsigned long long)(~skey) << 16)
                            | (unsigned)r;
    g_ckey_in[idx] = ckey;
}

// ---------------- kernel 2: fused gather + 16-warp greedy NMS (1 block / batch) ----
// dynamic smem: scand[PRE_NMS] float2 (48000 B) + skept[POST_NMS] float4 (4800 B)
__global__ void __launch_bounds__(NMS_THREADS)
nms_fused(float* __restrict__ out) {
    extern __shared__ unsigned char smem_raw[];
    float2* scand = (float2*)smem_raw;
    float4* skept = (float4*)(scand + PRE_NMS);
    __shared__ unsigned s_sup[NMS_WARPS];
    __shared__ unsigned s_rowp[NMS_WARPS][32];
    __shared__ int s_K;

    const int b    = blockIdx.x;
    const int tid  = threadIdx.x;
    const int wid  = tid >> 5;
    const int lane = tid & 31;

    // gather top-PRE_NMS boxes (sorted order) into shared; init output
    const unsigned long long* __restrict__ skeys = g_ckey_out + b * NPROP;
    for (int i = tid; i < PRE_NMS; i += NMS_THREADS) {
        int r = (int)(skeys[i] & 0xFFFFu);
        scand[i] = g_box[b * NPROP + r];
    }
    for (int i = tid; i < POST_NMS; i += NMS_THREADS) {
        float* o = out + (b * POST_NMS + i) * 3;
        o[0] = (float)b; o[1] = 0.0f; o[2] = 0.0f;
    }
    if (tid == 0) s_K = 0;
    __syncthreads();

    for (int c = 0; c < NCHUNK; ++c) {
        const int i = c * 32 + lane;
        const bool valid = (i < PRE_NMS);
        const int nvalid = PRE_NMS - c * 32;
        const unsigned validMask =
            (nvalid >= 32) ? FULLMASK : ((1u << nvalid) - 1u);

        float x1 = 0.0f, x2 = -2.0f;
        if (valid) { float2 t0 = scand[i]; x1 = t0.x; x2 = t0.y; }
        const float len = x2 - x1 + 1.0f;
        const int K = s_K;

        // ---- phase 1 (all 16 warps): candidate vs kept list, j strided by warp ----
        bool sup = !valid;
        int it = 0;
        for (int j = wid; j < K; j += NMS_WARPS) {
            float4 kb = skept[j];                    // broadcast within warp
            float inter = fminf(x2, kb.y) - fmaxf(x1, kb.x) + 1.0f;
            float uni = len + kb.z - inter;
            if (inter > 0.6999f * uni) {             // prefilter; decision by division
                if (inter / uni > NMS_THRESH_F) sup = true;
            }
            if (((++it) & 3) == 0 && __all_sync(FULLMASK, sup)) break;
        }
        {
            unsigned bal = __ballot_sync(FULLMASK, sup);
            if (lane == 0) s_sup[wid] = bal;
        }

        // ---- phase 2 (all 16 warps): split intra-chunk butterfly, <=2 offsets each ----
        {
            unsigned rowp = 0u;
            const int d0 = 2 * wid + 1;
            const int d1 = (2 * wid + 2 < 32) ? 2 * wid + 2 : 31;
            for (int d = d0; d <= d1; ++d) {
                float ox1 = __shfl_xor_sync(FULLMASK, x1, d);
                float ox2 = __shfl_xor_sync(FULLMASK, x2, d);
                float olen = ox2 - ox1 + 1.0f;
                float inter = fminf(x2, ox2) - fmaxf(x1, ox1) + 1.0f;
                float uni = len + olen - inter;
                if (inter > 0.6999f * uni) {
                    if (inter / uni > NMS_THRESH_F) rowp |= 1u << (lane ^ d);
                }
            }
            s_rowp[wid][lane] = rowp;
        }
        __syncthreads();

        // ---- phases 3-4 (warp 0 only): resolve + append ----
        if (wid == 0) {
            unsigned removed = ~validMask;
            #pragma unroll
            for (int w = 0; w < NMS_WARPS; ++w) removed |= s_sup[w];

            unsigned row = 0u;
            #pragma unroll
            for (int w = 0; w < NMS_WARPS; ++w) row |= s_rowp[w][lane];
            row &= validMask;

            // serial greedy resolution of the chunk
            unsigned keptbits = 0u;
            unsigned alive = ~removed;
            while (alive) {
                int p = __ffs(alive) - 1;                       // uniform
                keptbits |= 1u << p;
                unsigned rowp = __shfl_sync(FULLMASK, row, p);
                removed |= rowp;
                alive = ~removed & ~((2u << p) - 1u);
            }

            // append kept boxes
            int nk = __popc(keptbits);
            if (nk) {
                int myrank = K + __popc(keptbits & ((1u << lane) - 1u));
                if (((keptbits >> lane) & 1u) && myrank < POST_NMS) {
                    skept[myrank] = make_float4(x1, x2, len, 0.0f);
                    float* o = out + (b * POST_NMS + myrank) * 3;
                    o[1] = x1; o[2] = x2;
                }
                if (lane == 0) s_K = K + nk;
            }
        }
        __syncthreads();
        if (s_K >= POST_NMS) break;
    }
}

// ---------------- host launcher ----------------
extern "C" void kernel_launch(void* const* d_in, const int* in_sizes, int n_in,
                              void* d_out, int out_size) {
    (void)in_sizes; (void)n_in; (void)out_size;
    const float* scores = (const float*)d_in[0];
    const float* deltas = (const float*)d_in[1];
    float* out = (float*)d_out;

    unsigned long long *kin, *kout; void* tmp;
    cudaGetSymbolAddress((void**)&kin,  g_ckey_in);
    cudaGetSymbolAddress((void**)&kout, g_ckey_out);
    cudaGetSymbolAddress((void**)&tmp,  g_cub_temp);

    compute_props<<<(TOTAL + 255) / 256, 256>>>(scores, deltas);

    // full-device keys-only radix sort; bits [16,50) only (stability supplies the
    // r-ascending tie-break from input order) -> 5 onesweep passes
    size_t temp_bytes = sizeof(g_cub_temp);
    cub::DeviceRadixSort::SortKeys(
        tmp, temp_bytes,
        kin, kout, TOTAL,
        16, 50, (cudaStream_t)0);

    const int smem_bytes = PRE_NMS * (int)sizeof(float2) + POST_NMS * (int)sizeof(float4);
    cudaFuncSetAttribute(nms_fused, cudaFuncAttributeMaxDynamicSharedMemorySize, smem_bytes);
    nms_fused<<<BB, NMS_THREADS, smem_bytes>>>(out);
}